// round 6
// baseline (speedup 1.0000x reference)
#include <cuda_runtime.h>

#define B_ 4
#define T_ 12
#define N_ 2000
#define K_ 10
#define F_ 64
#define H_ 8

// Scratch: y = x @ W^T (24.6 MB). Static __device__ (no cudaMalloc allowed).
__device__ float g_y[B_ * T_ * N_ * F_];

// ---- packed-fp32 helpers (FFMA2 only reachable via PTX) ---------------------
__device__ __forceinline__ unsigned long long pk2(float a, float b) {
    unsigned long long r;
    asm("mov.b64 %0, {%1, %2};" : "=l"(r)
        : "r"(__float_as_uint(a)), "r"(__float_as_uint(b)));
    return r;
}
__device__ __forceinline__ unsigned long long ffma2(unsigned long long a,
                                                    unsigned long long b,
                                                    unsigned long long c) {
    unsigned long long d;
    asm("fma.rn.f32x2 %0, %1, %2, %3;" : "=l"(d) : "l"(a), "l"(b), "l"(c));
    return d;
}
__device__ __forceinline__ float2 upk2(unsigned long long a) {
    unsigned int lo, hi;
    asm("mov.b64 {%0, %1}, %2;" : "=r"(lo), "=r"(hi) : "l"(a));
    return make_float2(__uint_as_float(lo), __uint_as_float(hi));
}

// ---------------------------------------------------------------------------
// Kernel 1: y[row,f] = sum_fp x[row,fp] * W[f,fp].
// 750 blocks x 256 threads; 128-row tile; thread = 8 rows x 4 f (FFMA2 pairs).
// ---------------------------------------------------------------------------
__global__ __launch_bounds__(256) void k_xw(const float* __restrict__ x,
                                            const float* __restrict__ W) {
    __shared__ float xs[128][64];                  // 32 KB
    __shared__ unsigned long long Wp[64][32];      // 16 KB: Wp[fp][f2]=(W[2f2][fp],W[2f2+1][fp])

    const int tid = threadIdx.x;

    // Build Wp: thread = (f2 = tid>>3, col-group cg = tid&7 covering fp cg*8..+7).
    {
        const int f2 = tid >> 3, cg = tid & 7;
        const float* ra = W + (2 * f2) * 64 + cg * 8;
        const float* rb = W + (2 * f2 + 1) * 64 + cg * 8;
        const float4 a0 = *(const float4*)ra;
        const float4 a1 = *(const float4*)(ra + 4);
        const float4 b0 = *(const float4*)rb;
        const float4 b1 = *(const float4*)(rb + 4);
        Wp[cg * 8 + 0][f2] = pk2(a0.x, b0.x);
        Wp[cg * 8 + 1][f2] = pk2(a0.y, b0.y);
        Wp[cg * 8 + 2][f2] = pk2(a0.z, b0.z);
        Wp[cg * 8 + 3][f2] = pk2(a0.w, b0.w);
        Wp[cg * 8 + 4][f2] = pk2(a1.x, b1.x);
        Wp[cg * 8 + 5][f2] = pk2(a1.y, b1.y);
        Wp[cg * 8 + 6][f2] = pk2(a1.z, b1.z);
        Wp[cg * 8 + 7][f2] = pk2(a1.w, b1.w);
    }

    const size_t rbase = (size_t)blockIdx.x * 128;
    const float4* xg = (const float4*)(x + rbase * F_);
    #pragma unroll
    for (int j = tid; j < 128 * 16; j += 256) {              // coalesced
        ((float4*)xs)[j] = xg[j];
    }
    __syncthreads();

    const int fx = tid & 15;       // f chunk: 4 floats = 2 ull
    const int rg = tid >> 4;       // rows rg*8 .. rg*8+7

    unsigned long long acc[8][2];
    #pragma unroll
    for (int r = 0; r < 8; ++r) { acc[r][0] = 0ull; acc[r][1] = 0ull; }

    #pragma unroll 4
    for (int fps = 0; fps < 16; ++fps) {
        const int fp = fps * 4;
        unsigned long long w0[4], w1[4];
        #pragma unroll
        for (int i = 0; i < 4; ++i) {
            const ulonglong2 wv = *(const ulonglong2*)&Wp[fp + i][fx * 2];
            w0[i] = wv.x; w1[i] = wv.y;            // conflict-free
        }
        #pragma unroll
        for (int r = 0; r < 8; ++r) {
            const float4 xv = *(const float4*)&xs[rg * 8 + r][fp];   // broadcast
            unsigned long long xd;
            xd = pk2(xv.x, xv.x);
            acc[r][0] = ffma2(xd, w0[0], acc[r][0]); acc[r][1] = ffma2(xd, w1[0], acc[r][1]);
            xd = pk2(xv.y, xv.y);
            acc[r][0] = ffma2(xd, w0[1], acc[r][0]); acc[r][1] = ffma2(xd, w1[1], acc[r][1]);
            xd = pk2(xv.z, xv.z);
            acc[r][0] = ffma2(xd, w0[2], acc[r][0]); acc[r][1] = ffma2(xd, w1[2], acc[r][1]);
            xd = pk2(xv.w, xv.w);
            acc[r][0] = ffma2(xd, w0[3], acc[r][0]); acc[r][1] = ffma2(xd, w1[3], acc[r][1]);
        }
    }

    float* yp = g_y + rbase * F_;
    #pragma unroll
    for (int r = 0; r < 8; ++r) {
        const float2 lo = upk2(acc[r][0]);
        const float2 hi = upk2(acc[r][1]);
        *(float4*)&yp[(rg * 8 + r) * F_ + fx * 4] = make_float4(lo.x, lo.y, hi.x, hi.y);
    }
}

// ---------------------------------------------------------------------------
// Kernel 2: gather + heads + blend + relu. Thread = (node nl, head-pair hp,
// float4 f4). f32x2 packs adjacent f's (LDG.128 register pairs feed FFMA2
// directly). Duplicated weight pairs live in SMEM (ulonglong2 per (nl,k,hp)),
// read by one broadcast LDS.128 per k — frees ~40 regs vs R5 so we fit
// 4 CTAs/SM. Gather indices live in registers. prev carries the UNBLENDED
// agg[t-1]; t=0 peeled.
// ---------------------------------------------------------------------------
__global__ __launch_bounds__(256, 4) void k_gather(
    const float* __restrict__ dist,
    const float* __restrict__ bias,
    const int* __restrict__ nidx,          // int32 (JAX x64 disabled)
    float* __restrict__ out) {

    __shared__ ulonglong2 swd[4][K_][4];   // [nl][k][hp] = (dup(w_2hp), dup(w_2hp+1))

    const int tid = threadIdx.x;
    const int f4  = tid & 15;
    const int hp  = (tid >> 4) & 3;        // heads 2hp, 2hp+1
    const int nl  = tid >> 6;              // 0..3
    const int bb  = blockIdx.y;
    const int n   = blockIdx.x * 4 + nl;

    // Cooperative weight-table build: 160 entries, one per (nl,k,hp).
    if (tid < 4 * K_ * 4) {
        const int e_nl = tid / (K_ * 4);
        const int e_k  = (tid >> 2) % K_;
        const int e_hp = tid & 3;
        const float d = __ldg(&dist[(blockIdx.x * 4 + e_nl) * K_ + e_k]);
        const float e = -d * d * (1.0f / (H_ * 36.0f));
        const float w0 = __expf(e * (float)(2 * e_hp + 1));
        const float w1 = __expf(e * (float)(2 * e_hp + 2));
        swd[e_nl][e_k][e_hp] = make_ulonglong2(pk2(w0, w0), pk2(w1, w1));
    }

    // Gather indices in registers (broadcast loads; 10 regs).
    int sx[K_];
    #pragma unroll
    for (int k = 0; k < K_; ++k)
        sx[k] = __ldg(&nidx[n * K_ + k]) * (F_ / 4);   // pre-scaled float4 idx

    __syncthreads();

    const float4 bv = *(const float4*)(bias + f4 * 4);
    const unsigned long long b01 = pk2(bv.x, bv.y);     // natural pairs
    const unsigned long long b23 = pk2(bv.z, bv.w);

    const ulonglong2* wrow = swd[nl][0] + hp;           // stride K_*... index k*4
    const size_t obase = ((size_t)(bb * T_ * N_) + n) * (H_ * F_) + (2 * hp) * F_ + f4 * 4;
    const float4* ybase = (const float4*)g_y + (size_t)(bb * T_) * N_ * (F_ / 4) + f4;

    unsigned long long prev[2][2];
    unsigned long long acc[2][2];

    // ---- t = 0: out = relu(acc + b), prev = acc ----
    {
        acc[0][0] = 0ull; acc[0][1] = 0ull; acc[1][0] = 0ull; acc[1][1] = 0ull;
        #pragma unroll
        for (int k = 0; k < K_; ++k) {                  // 10 independent LDG.128
            const float4 yv = __ldg(&ybase[sx[k]]);
            const ulonglong2 wd = wrow[k * 4];          // LDS.128 broadcast
            const unsigned long long y01 = pk2(yv.x, yv.y);
            const unsigned long long y23 = pk2(yv.z, yv.w);
            acc[0][0] = ffma2(y01, wd.x, acc[0][0]);
            acc[0][1] = ffma2(y23, wd.x, acc[0][1]);
            acc[1][0] = ffma2(y01, wd.y, acc[1][0]);
            acc[1][1] = ffma2(y23, wd.y, acc[1][1]);
        }
        const unsigned long long one = pk2(1.f, 1.f);
        float* ob = out + obase;
        #pragma unroll
        for (int h = 0; h < 2; ++h) {
            const float2 lo = upk2(ffma2(acc[h][0], one, b01));
            const float2 hi = upk2(ffma2(acc[h][1], one, b23));
            *(float4*)(ob + h * F_) =
                make_float4(fmaxf(lo.x, 0.f), fmaxf(lo.y, 0.f),
                            fmaxf(hi.x, 0.f), fmaxf(hi.y, 0.f));
            prev[h][0] = acc[h][0]; prev[h][1] = acc[h][1];
        }
    }

    const unsigned long long c0d = pk2(0.8f, 0.8f);
    const unsigned long long c1d = pk2(0.2f, 0.2f);

    #pragma unroll 1
    for (int t = 1; t < T_; ++t) {
        const float4* yb = ybase + (size_t)t * N_ * (F_ / 4);
        acc[0][0] = 0ull; acc[0][1] = 0ull; acc[1][0] = 0ull; acc[1][1] = 0ull;
        #pragma unroll
        for (int k = 0; k < K_; ++k) {
            const float4 yv = __ldg(&yb[sx[k]]);
            const ulonglong2 wd = wrow[k * 4];
            const unsigned long long y01 = pk2(yv.x, yv.y);
            const unsigned long long y23 = pk2(yv.z, yv.w);
            acc[0][0] = ffma2(y01, wd.x, acc[0][0]);
            acc[0][1] = ffma2(y23, wd.x, acc[0][1]);
            acc[1][0] = ffma2(y01, wd.y, acc[1][0]);
            acc[1][1] = ffma2(y23, wd.y, acc[1][1]);
        }

        float* ob = out + obase + (size_t)t * N_ * (H_ * F_);
        #pragma unroll
        for (int h = 0; h < 2; ++h) {
            const float2 lo = upk2(ffma2(acc[h][0], c0d, ffma2(prev[h][0], c1d, b01)));
            const float2 hi = upk2(ffma2(acc[h][1], c0d, ffma2(prev[h][1], c1d, b23)));
            *(float4*)(ob + h * F_) =
                make_float4(fmaxf(lo.x, 0.f), fmaxf(lo.y, 0.f),
                            fmaxf(hi.x, 0.f), fmaxf(hi.y, 0.f));
            prev[h][0] = acc[h][0]; prev[h][1] = acc[h][1];   // UNBLENDED carry
        }
    }
}

// ---------------------------------------------------------------------------
// Inputs: x f32[4,12,2000,64], neighbor_dist f32[2000,10], W f32[64,64],
// b f32[64], neighbor_idx i32[2000,10]. Output f32[4,12,2000,8,64].
// ---------------------------------------------------------------------------
extern "C" void kernel_launch(void* const* d_in, const int* in_sizes, int n_in,
                              void* d_out, int out_size) {
    const float* x    = (const float*)d_in[0];
    const float* dist = (const float*)d_in[1];
    const float* W    = (const float*)d_in[2];
    const float* bias = (const float*)d_in[3];
    const int*   nidx = (const int*)d_in[4];
    float*       out  = (float*)d_out;

    k_xw<<<(B_ * T_ * N_) / 128, 256>>>(x, W);

    dim3 g2(N_ / 4, B_);
    k_gather<<<g2, 256>>>(dist, bias, nidx, out);
}